// round 9
// baseline (speedup 1.0000x reference)
#include <cuda_runtime.h>
#include <cstdint>

#define N_NODES 50000
#define N_EDGES_MAX 1600000
#define D 128
#define EPS 0.001f
#define SCAN_BLOCKS ((N_NODES + 1023) / 1024 + 1)
#define MAX_TILES ((N_NODES + 127) / 128)

// Scratch (allocation-free rule: __device__ globals)
__device__ float g_h[(size_t)N_NODES * D];
__device__ int   g_degcnt[N_NODES];
__device__ int   g_off[N_NODES + 1];
__device__ int   g_cur[N_NODES];
__device__ int   g_csrc[N_EDGES_MAX];
__device__ int   g_bsum[SCAN_BLOCKS];
__device__ int   g_tilecnt[MAX_TILES];     // per-tile aggregated-row counter
__device__ int   g_is64;

// Packed f32x2 FMA (family-common on sm_100+; FFMA2 in SASS, PTX-only path)
__device__ __forceinline__ void ffma2(unsigned long long& d,
                                      unsigned long long a,
                                      unsigned long long b) {
    asm("fma.rn.f32x2 %0, %1, %2, %0;" : "+l"(d) : "l"(a), "l"(b));
}
__device__ __forceinline__ unsigned long long pack_dup(float v) {
    unsigned long long p;
    asm("mov.b64 %0, {%1, %1};" : "=l"(p) : "r"(__float_as_uint(v)));
    return p;
}
__device__ __forceinline__ void unpack2(unsigned long long p, float& lo, float& hi) {
    uint32_t a, b;
    asm("mov.b64 {%0, %1}, %2;" : "=r"(a), "=r"(b) : "l"(p));
    lo = __uint_as_float(a);
    hi = __uint_as_float(b);
}

// ===========================================================================
// CSR build (unchanged — validated)
// ===========================================================================
__global__ void detect_kernel(const int* __restrict__ e32) {
    if (threadIdx.x == 0 && blockIdx.x == 0) {
        int is64 = 1;
        #pragma unroll 1
        for (int k = 1; k < 128; k += 2) {
            if (e32[k] != 0) { is64 = 0; break; }
        }
        g_is64 = is64;
    }
}

__global__ void zero_deg_kernel(int* __restrict__ degcnt, int n,
                                int* __restrict__ tilecnt, int ntiles) {
    int i = blockIdx.x * blockDim.x + threadIdx.x;
    if (i < n) degcnt[i] = 0;
    if (i < ntiles) tilecnt[i] = 0;
}

__global__ void hist_kernel(const void* __restrict__ ei, int E,
                            int* __restrict__ degcnt) {
    int i = blockIdx.x * blockDim.x + threadIdx.x;
    if (i >= E) return;
    int dd;
    if (g_is64) dd = (int)reinterpret_cast<const long long*>(ei)[(size_t)E + i];
    else        dd = reinterpret_cast<const int*>(ei)[(size_t)E + i];
    atomicAdd(degcnt + dd, 1);
}

__global__ void scan_part_kernel(const int* __restrict__ degcnt,
                                 int* __restrict__ off,
                                 int* __restrict__ bsum, int N) {
    __shared__ int wsum[32];
    const int tid = threadIdx.x, lane = tid & 31, wid = tid >> 5;
    int idx = blockIdx.x * 1024 + tid;
    int v = (idx < N) ? degcnt[idx] : 0;
    int incl = v;
    #pragma unroll
    for (int o = 1; o < 32; o <<= 1) {
        int t = __shfl_up_sync(0xffffffffu, incl, o);
        if (lane >= o) incl += t;
    }
    if (lane == 31) wsum[wid] = incl;
    __syncthreads();
    if (wid == 0) {
        int s = wsum[lane];
        #pragma unroll
        for (int o = 1; o < 32; o <<= 1) {
            int t = __shfl_up_sync(0xffffffffu, s, o);
            if (lane >= o) s += t;
        }
        wsum[lane] = s;
    }
    __syncthreads();
    int woff = wid ? wsum[wid - 1] : 0;
    if (idx < N) off[idx] = woff + incl - v;
    if (tid == 1023) bsum[blockIdx.x] = woff + incl;
}

__global__ void scan_tops_kernel(int* __restrict__ bsum, int nb) {
    const int tid = threadIdx.x, lane = tid & 31;
    int v = (tid < nb) ? bsum[tid] : 0;
    int incl = v;
    #pragma unroll
    for (int o = 1; o < 32; o <<= 1) {
        int t = __shfl_up_sync(0xffffffffu, incl, o);
        if (lane >= o) incl += t;
    }
    __shared__ int w0_total;
    if (tid == 31) w0_total = incl;
    __syncthreads();
    int base = (tid >= 32) ? w0_total : 0;
    if (tid < nb) bsum[tid] = base + incl - v;
    if (tid == nb - 1) bsum[nb] = base + incl;
}

__global__ void scan_add_kernel(int* __restrict__ off, int* __restrict__ cur,
                                const int* __restrict__ bsum, int N, int nb) {
    int idx = blockIdx.x * 1024 + threadIdx.x;
    if (idx < N) {
        int v = off[idx] + bsum[blockIdx.x];
        off[idx] = v;
        cur[idx] = v;
    }
    if (idx == 0) off[N] = bsum[nb];
}

__global__ void fill_kernel(const void* __restrict__ ei, int E,
                            int* __restrict__ cur, int* __restrict__ csrc) {
    int i = blockIdx.x * blockDim.x + threadIdx.x;
    if (i >= E) return;
    int ss, dd;
    if (g_is64) {
        const long long* e = reinterpret_cast<const long long*>(ei);
        ss = (int)e[i];
        dd = (int)e[(size_t)E + i];
    } else {
        const int* e = reinterpret_cast<const int*>(ei);
        ss = e[i];
        dd = e[(size_t)E + i];
    }
    int pos = atomicAdd(cur + dd, 1);
    csrc[pos] = ss;
}

// ---------------------------------------------------------------------------
// Aggregate one node's row (warp-collective helper; identical math everywhere
// so producer and fallback produce bitwise-identical fp32 results).
// ---------------------------------------------------------------------------
__device__ __forceinline__ float4 agg_row(const float* __restrict__ x,
                                          const int* __restrict__ csrc,
                                          const int* __restrict__ off,
                                          int node, int lane) {
    float4 acc = *reinterpret_cast<const float4*>(x + (size_t)node * D + lane * 4);
    const float sc = 1.0f + EPS;
    acc.x *= sc; acc.y *= sc; acc.z *= sc; acc.w *= sc;
    int j = off[node];
    const int e = off[node + 1];
    for (; j + 4 <= e; j += 4) {
        int a0 = __ldg(csrc + j),     a1 = __ldg(csrc + j + 1);
        int a2 = __ldg(csrc + j + 2), a3 = __ldg(csrc + j + 3);
        float4 v0 = *reinterpret_cast<const float4*>(x + (size_t)a0 * D + lane * 4);
        float4 v1 = *reinterpret_cast<const float4*>(x + (size_t)a1 * D + lane * 4);
        float4 v2 = *reinterpret_cast<const float4*>(x + (size_t)a2 * D + lane * 4);
        float4 v3 = *reinterpret_cast<const float4*>(x + (size_t)a3 * D + lane * 4);
        acc.x += (v0.x + v1.x) + (v2.x + v3.x);
        acc.y += (v0.y + v1.y) + (v2.y + v3.y);
        acc.z += (v0.z + v1.z) + (v2.z + v3.z);
        acc.w += (v0.w + v1.w) + (v2.w + v3.w);
    }
    for (; j < e; j++) {
        int a0 = __ldg(csrc + j);
        float4 v0 = *reinterpret_cast<const float4*>(x + (size_t)a0 * D + lane * 4);
        acc.x += v0.x; acc.y += v0.y; acc.z += v0.z; acc.w += v0.w;
    }
    return acc;
}

// ---------------------------------------------------------------------------
// Producer: warp per node; release per-tile counter after storing the row.
// ---------------------------------------------------------------------------
__global__ void agg_kernel(const float* __restrict__ x,
                           const int* __restrict__ csrc,
                           const int* __restrict__ off,
                           float* __restrict__ h,
                           int* __restrict__ tilecnt, int N) {
    int w = (blockIdx.x * blockDim.x + threadIdx.x) >> 5;
    int lane = threadIdx.x & 31;
    if (w >= N) return;
    float4 acc = agg_row(x, csrc, off, w, lane);
    *reinterpret_cast<float4*>(h + (size_t)w * D + lane * 4) = acc;
    __threadfence();                       // release: row before counter
    if (lane == 0) atomicAdd(tilecnt + (w >> 7), 1);
}

// ===========================================================================
// Consumer MLP (R7 structure): waits per-tile, FFMA2 GEMMs, fused epilogues.
// Fallback: if the tile never becomes ready (scheduler serialization),
// recompute it locally with identical math — hang-proof, deterministic.
// ===========================================================================
__global__ void __launch_bounds__(256, 2)
mlp_kernel(const float* __restrict__ x,
           const int* __restrict__ csrc,
           const int* __restrict__ off,
           const float* __restrict__ H,
           const int* __restrict__ tilecnt,
           const float* __restrict__ W1, const float* __restrict__ b1,
           const float* __restrict__ W2, const float* __restrict__ b2,
           float* __restrict__ out, int M) {
    extern __shared__ float sm[];
    float* As = sm;                    // [16][132]
    float* Bs = As + 16 * 132;         // [16][128]
    float* Hs = Bs + 16 * 128;         // [128][132]

    const int tid = threadIdx.x;
    const int tile = blockIdx.x;
    const int row_base = tile * 128;
    const int expected = (M - row_base < 128) ? (M - row_base) : 128;

    // ---- tile-ready wait (bounded) ----
    __shared__ int s_ready;
    if (tid == 0) {
        s_ready = 1;
        const volatile int* cnt = tilecnt + tile;
        long long it = 0;
        while (*cnt < expected) {
            __nanosleep(128);
            if (++it > 4000000ll) { s_ready = 0; break; }
        }
        __threadfence();               // acquire: counter before row reads
    }
    __syncthreads();

    if (!s_ready) {
        // Fallback: self-aggregate this tile (bitwise-identical values).
        const int wid = tid >> 5, lane = tid & 31;
        #pragma unroll 1
        for (int t = 0; t < 16; t++) {
            int node = row_base + wid * 16 + t;
            if (node < M) {
                float4 acc = agg_row(x, csrc, off, node, lane);
                *reinterpret_cast<float4*>(const_cast<float*>(H) +
                    (size_t)node * D + lane * 4) = acc;
            }
        }
        __syncthreads();
    }

    const int tx = tid & 15;
    const int ty = tid >> 4;
    const int col0 = tx * 8;

    unsigned long long acc[8][4];
    #pragma unroll
    for (int i = 0; i < 8; i++)
        #pragma unroll
        for (int j = 0; j < 4; j++) acc[i][j] = 0ull;

    // ---------------- GEMM1: acc = H_tile @ W1 ----------------
    for (int kk = 0; kk < 128; kk += 16) {
        #pragma unroll
        for (int i = 0; i < 2; i++) {
            int f = tid * 2 + i;
            int m  = f >> 2;
            int kq = f & 3;
            int grow = row_base + m;
            float4 va = make_float4(0.f, 0.f, 0.f, 0.f);
            if (grow < M)
                va = *reinterpret_cast<const float4*>(H + (size_t)grow * D + kk + kq * 4);
            As[(kq * 4 + 0) * 132 + m] = va.x;
            As[(kq * 4 + 1) * 132 + m] = va.y;
            As[(kq * 4 + 2) * 132 + m] = va.z;
            As[(kq * 4 + 3) * 132 + m] = va.w;
            int kb = f >> 5;
            int n4 = f & 31;
            *reinterpret_cast<float4*>(Bs + kb * 128 + n4 * 4) =
                *reinterpret_cast<const float4*>(W1 + (size_t)(kk + kb) * D + n4 * 4);
        }
        __syncthreads();

        #pragma unroll
        for (int k = 0; k < 16; k++) {
            float4 a01 = *reinterpret_cast<const float4*>(As + k * 132 + ty * 8);
            float4 a23 = *reinterpret_cast<const float4*>(As + k * 132 + ty * 8 + 4);
            const unsigned long long* bp =
                reinterpret_cast<const unsigned long long*>(Bs + k * 128 + col0);
            unsigned long long bv0 = bp[0], bv1 = bp[1], bv2 = bp[2], bv3 = bp[3];
            float a[8] = {a01.x, a01.y, a01.z, a01.w, a23.x, a23.y, a23.z, a23.w};
            #pragma unroll
            for (int i = 0; i < 8; i++) {
                unsigned long long ap = pack_dup(a[i]);
                ffma2(acc[i][0], ap, bv0);
                ffma2(acc[i][1], ap, bv1);
                ffma2(acc[i][2], ap, bv2);
                ffma2(acc[i][3], ap, bv3);
            }
        }
        __syncthreads();
    }

    // Epilogue 1: bias + relu -> Hs
    {
        float bv[8];
        #pragma unroll
        for (int j = 0; j < 8; j++) bv[j] = b1[col0 + j];
        #pragma unroll
        for (int i = 0; i < 8; i++) {
            int row = ty * 8 + i;
            float o[8];
            #pragma unroll
            for (int j = 0; j < 4; j++) {
                unpack2(acc[i][j], o[2 * j], o[2 * j + 1]);
                acc[i][j] = 0ull;
            }
            float4 o0, o1;
            o0.x = fmaxf(o[0] + bv[0], 0.f);
            o0.y = fmaxf(o[1] + bv[1], 0.f);
            o0.z = fmaxf(o[2] + bv[2], 0.f);
            o0.w = fmaxf(o[3] + bv[3], 0.f);
            o1.x = fmaxf(o[4] + bv[4], 0.f);
            o1.y = fmaxf(o[5] + bv[5], 0.f);
            o1.z = fmaxf(o[6] + bv[6], 0.f);
            o1.w = fmaxf(o[7] + bv[7], 0.f);
            *reinterpret_cast<float4*>(Hs + row * 132 + col0)     = o0;
            *reinterpret_cast<float4*>(Hs + row * 132 + col0 + 4) = o1;
        }
    }
    __syncthreads();

    // ---------------- GEMM2: acc = Hs @ W2 ----------------
    for (int kk = 0; kk < 128; kk += 16) {
        #pragma unroll
        for (int i = 0; i < 2; i++) {
            int f = tid * 2 + i;
            int kb = f >> 5;
            int n4 = f & 31;
            *reinterpret_cast<float4*>(Bs + kb * 128 + n4 * 4) =
                *reinterpret_cast<const float4*>(W2 + (size_t)(kk + kb) * D + n4 * 4);
        }
        __syncthreads();

        #pragma unroll
        for (int k = 0; k < 16; k++) {
            const unsigned long long* bp =
                reinterpret_cast<const unsigned long long*>(Bs + k * 128 + col0);
            unsigned long long bv0 = bp[0], bv1 = bp[1], bv2 = bp[2], bv3 = bp[3];
            #pragma unroll
            for (int i = 0; i < 8; i++) {
                unsigned long long ap = pack_dup(Hs[(ty * 8 + i) * 132 + kk + k]);
                ffma2(acc[i][0], ap, bv0);
                ffma2(acc[i][1], ap, bv1);
                ffma2(acc[i][2], ap, bv2);
                ffma2(acc[i][3], ap, bv3);
            }
        }
        __syncthreads();
    }

    // Epilogue 2: bias -> out
    {
        float bv[8];
        #pragma unroll
        for (int j = 0; j < 8; j++) bv[j] = b2[col0 + j];
        #pragma unroll
        for (int i = 0; i < 8; i++) {
            int r = row_base + ty * 8 + i;
            if (r < M) {
                float o[8];
                #pragma unroll
                for (int j = 0; j < 4; j++)
                    unpack2(acc[i][j], o[2 * j], o[2 * j + 1]);
                float4 o0, o1;
                o0.x = o[0] + bv[0];
                o0.y = o[1] + bv[1];
                o0.z = o[2] + bv[2];
                o0.w = o[3] + bv[3];
                o1.x = o[4] + bv[4];
                o1.y = o[5] + bv[5];
                o1.z = o[6] + bv[6];
                o1.w = o[7] + bv[7];
                *reinterpret_cast<float4*>(out + (size_t)r * D + col0)     = o0;
                *reinterpret_cast<float4*>(out + (size_t)r * D + col0 + 4) = o1;
            }
        }
    }
}

extern "C" void kernel_launch(void* const* d_in, const int* in_sizes, int n_in,
                              void* d_out, int out_size) {
    const float* x  = (const float*)d_in[0];
    const void*  ei = d_in[1];
    const float* W1 = (const float*)d_in[2];
    const float* b1 = (const float*)d_in[3];
    const float* W2 = (const float*)d_in[4];
    const float* b2 = (const float*)d_in[5];
    float* out = (float*)d_out;

    const int N = in_sizes[0] / D;
    const int E = in_sizes[1] / 2;
    const int nb = (N + 1023) / 1024;
    const int ntiles = (N + 127) / 128;

    float* p_h    = nullptr;
    int*   p_deg  = nullptr;
    int*   p_off  = nullptr;
    int*   p_cur  = nullptr;
    int*   p_csrc = nullptr;
    int*   p_bsum = nullptr;
    int*   p_tcnt = nullptr;
    cudaGetSymbolAddress((void**)(&p_h),    g_h);
    cudaGetSymbolAddress((void**)(&p_deg),  g_degcnt);
    cudaGetSymbolAddress((void**)(&p_off),  g_off);
    cudaGetSymbolAddress((void**)(&p_cur),  g_cur);
    cudaGetSymbolAddress((void**)(&p_csrc), g_csrc);
    cudaGetSymbolAddress((void**)(&p_bsum), g_bsum);
    cudaGetSymbolAddress((void**)(&p_tcnt), g_tilecnt);

    const int smem_mlp = (16 * 132 + 16 * 128 + 128 * 132) * (int)sizeof(float);

    static cudaStream_t s2;
    static cudaEvent_t ev_fork, ev_join;
    static int once = 0;
    if (!once) {
        cudaFuncSetAttribute(mlp_kernel,
                             cudaFuncAttributeMaxDynamicSharedMemorySize,
                             smem_mlp);
        int lo, hi;
        cudaDeviceGetStreamPriorityRange(&lo, &hi);   // lo = lowest priority
        cudaStreamCreateWithPriority(&s2, cudaStreamNonBlocking, lo);
        cudaEventCreateWithFlags(&ev_fork, cudaEventDisableTiming);
        cudaEventCreateWithFlags(&ev_join, cudaEventDisableTiming);
        once = 1;
    }

    // ---- serial prologue: CSR build ----
    detect_kernel<<<1, 32>>>((const int*)ei);
    zero_deg_kernel<<<(N + 255) / 256, 256>>>(p_deg, N, p_tcnt, ntiles);
    hist_kernel<<<(E + 255) / 256, 256>>>(ei, E, p_deg);
    scan_part_kernel<<<nb, 1024>>>(p_deg, p_off, p_bsum, N);
    scan_tops_kernel<<<1, 64>>>(p_bsum, nb);
    scan_add_kernel<<<nb, 1024>>>(p_off, p_cur, p_bsum, N, nb);
    fill_kernel<<<(E + 255) / 256, 256>>>(ei, E, p_cur, p_csrc);

    // ---- fork: agg on main stream, MLP consumer on low-priority stream ----
    cudaEventRecord(ev_fork, 0);
    cudaStreamWaitEvent(s2, ev_fork, 0);

    agg_kernel<<<(N + 7) / 8, 256>>>(x, p_csrc, p_off, p_h, p_tcnt, N);

    mlp_kernel<<<ntiles, 256, smem_mlp, s2>>>(x, p_csrc, p_off, p_h, p_tcnt,
                                              W1, b1, W2, b2, out, N);

    // ---- join ----
    cudaEventRecord(ev_join, s2);
    cudaStreamWaitEvent(0, ev_join, 0);
}

// round 10
// speedup vs baseline: 1.3199x; 1.3199x over previous
#include <cuda_runtime.h>
#include <cuda_bf16.h>
#include <cstdint>

#define N_NODES 50000
#define N_EDGES_MAX 1600000
#define D 128
#define EPS 0.001f
#define SCAN_BLOCKS ((N_NODES + 1023) / 1024 + 1)

// Scratch (allocation-free rule: __device__ globals)
__device__ float g_h[(size_t)N_NODES * D];
__device__ int   g_degcnt[N_NODES];
__device__ int   g_off[N_NODES + 1];
__device__ int   g_cur[N_NODES];
__device__ int   g_csrc[N_EDGES_MAX];
__device__ int   g_bsum[SCAN_BLOCKS];
__device__ int   g_is64;

// ===========================================================================
// CSR build + aggregation (byte-identical to the R7 pass)
// ===========================================================================
__global__ void detect_kernel(const int* __restrict__ e32) {
    if (threadIdx.x == 0 && blockIdx.x == 0) {
        int is64 = 1;
        #pragma unroll 1
        for (int k = 1; k < 128; k += 2) {
            if (e32[k] != 0) { is64 = 0; break; }
        }
        g_is64 = is64;
    }
}

__global__ void zero_deg_kernel(int* __restrict__ degcnt, int n) {
    int i = blockIdx.x * blockDim.x + threadIdx.x;
    if (i < n) degcnt[i] = 0;
}

__global__ void hist_kernel(const void* __restrict__ ei, int E,
                            int* __restrict__ degcnt) {
    int i = blockIdx.x * blockDim.x + threadIdx.x;
    if (i >= E) return;
    int dd;
    if (g_is64) dd = (int)reinterpret_cast<const long long*>(ei)[(size_t)E + i];
    else        dd = reinterpret_cast<const int*>(ei)[(size_t)E + i];
    atomicAdd(degcnt + dd, 1);
}

__global__ void scan_part_kernel(const int* __restrict__ degcnt,
                                 int* __restrict__ off,
                                 int* __restrict__ bsum, int N) {
    __shared__ int wsum[32];
    const int tid = threadIdx.x, lane = tid & 31, wid = tid >> 5;
    int idx = blockIdx.x * 1024 + tid;
    int v = (idx < N) ? degcnt[idx] : 0;
    int incl = v;
    #pragma unroll
    for (int o = 1; o < 32; o <<= 1) {
        int t = __shfl_up_sync(0xffffffffu, incl, o);
        if (lane >= o) incl += t;
    }
    if (lane == 31) wsum[wid] = incl;
    __syncthreads();
    if (wid == 0) {
        int s = wsum[lane];
        #pragma unroll
        for (int o = 1; o < 32; o <<= 1) {
            int t = __shfl_up_sync(0xffffffffu, s, o);
            if (lane >= o) s += t;
        }
        wsum[lane] = s;
    }
    __syncthreads();
    int woff = wid ? wsum[wid - 1] : 0;
    if (idx < N) off[idx] = woff + incl - v;
    if (tid == 1023) bsum[blockIdx.x] = woff + incl;
}

__global__ void scan_tops_kernel(int* __restrict__ bsum, int nb) {
    const int tid = threadIdx.x, lane = tid & 31;
    int v = (tid < nb) ? bsum[tid] : 0;
    int incl = v;
    #pragma unroll
    for (int o = 1; o < 32; o <<= 1) {
        int t = __shfl_up_sync(0xffffffffu, incl, o);
        if (lane >= o) incl += t;
    }
    __shared__ int w0_total;
    if (tid == 31) w0_total = incl;
    __syncthreads();
    int base = (tid >= 32) ? w0_total : 0;
    if (tid < nb) bsum[tid] = base + incl - v;
    if (tid == nb - 1) bsum[nb] = base + incl;
}

__global__ void scan_add_kernel(int* __restrict__ off, int* __restrict__ cur,
                                const int* __restrict__ bsum, int N, int nb) {
    int idx = blockIdx.x * 1024 + threadIdx.x;
    if (idx < N) {
        int v = off[idx] + bsum[blockIdx.x];
        off[idx] = v;
        cur[idx] = v;
    }
    if (idx == 0) off[N] = bsum[nb];
}

__global__ void fill_kernel(const void* __restrict__ ei, int E,
                            int* __restrict__ cur, int* __restrict__ csrc) {
    int i = blockIdx.x * blockDim.x + threadIdx.x;
    if (i >= E) return;
    int ss, dd;
    if (g_is64) {
        const long long* e = reinterpret_cast<const long long*>(ei);
        ss = (int)e[i];
        dd = (int)e[(size_t)E + i];
    } else {
        const int* e = reinterpret_cast<const int*>(ei);
        ss = e[i];
        dd = e[(size_t)E + i];
    }
    int pos = atomicAdd(cur + dd, 1);
    csrc[pos] = ss;
}

__global__ void agg_kernel(const float* __restrict__ x,
                           const int* __restrict__ csrc,
                           const int* __restrict__ off,
                           float* __restrict__ h, int N) {
    int w = (blockIdx.x * blockDim.x + threadIdx.x) >> 5;
    int lane = threadIdx.x & 31;
    if (w >= N) return;

    float4 acc = *reinterpret_cast<const float4*>(x + (size_t)w * D + lane * 4);
    const float sc = 1.0f + EPS;
    acc.x *= sc; acc.y *= sc; acc.z *= sc; acc.w *= sc;

    int j = off[w];
    const int e = off[w + 1];
    for (; j + 4 <= e; j += 4) {
        int a0 = __ldg(csrc + j),     a1 = __ldg(csrc + j + 1);
        int a2 = __ldg(csrc + j + 2), a3 = __ldg(csrc + j + 3);
        float4 v0 = *reinterpret_cast<const float4*>(x + (size_t)a0 * D + lane * 4);
        float4 v1 = *reinterpret_cast<const float4*>(x + (size_t)a1 * D + lane * 4);
        float4 v2 = *reinterpret_cast<const float4*>(x + (size_t)a2 * D + lane * 4);
        float4 v3 = *reinterpret_cast<const float4*>(x + (size_t)a3 * D + lane * 4);
        acc.x += (v0.x + v1.x) + (v2.x + v3.x);
        acc.y += (v0.y + v1.y) + (v2.y + v3.y);
        acc.z += (v0.z + v1.z) + (v2.z + v3.z);
        acc.w += (v0.w + v1.w) + (v2.w + v3.w);
    }
    for (; j < e; j++) {
        int a0 = __ldg(csrc + j);
        float4 v0 = *reinterpret_cast<const float4*>(x + (size_t)a0 * D + lane * 4);
        acc.x += v0.x; acc.y += v0.y; acc.z += v0.z; acc.w += v0.w;
    }
    *reinterpret_cast<float4*>(h + (size_t)w * D + lane * 4) = acc;
}

// ===========================================================================
// Tensor-core MLP via family-common mma.sync (bf16, 3-pass hi/lo split).
//   out = relu(H@W1+b1) @ W2 + b2, 128-row tile per CTA, 256 threads, 8 warps.
// Warp grid 4(m)x2(n): each warp owns 32 rows x 64 cols = 2 mtiles x 8 ntiles.
// SMEM: Ah/Al [128][136 bf16] (A split), Bh/Bl [128n][18 bf16] (W chunk,
// transposed for col-major B frags), bias1/bias2.
// ===========================================================================
#define LDA32 68                 // uint32 stride of Ah/Al rows (136 bf16)
#define LDB32 9                  // uint32 stride of Bn rows (18 bf16)
#define SM_BIAS1 0
#define SM_BIAS2 512
#define SM_AH    1024
#define SM_AL    (SM_AH + 128 * LDA32 * 4)          // +34816
#define SM_BH    (SM_AL + 128 * LDA32 * 4)
#define SM_BL    (SM_BH + 128 * LDB32 * 4)          // +4608
#define SM_MLP_TOTAL (SM_BL + 128 * LDB32 * 4)      // 79872 bytes

__device__ __forceinline__ void split_pair(float v0, float v1,
                                           uint32_t& hi, uint32_t& lo) {
    __nv_bfloat16 h0 = __float2bfloat16(v0);
    __nv_bfloat16 h1 = __float2bfloat16(v1);
    __nv_bfloat16 l0 = __float2bfloat16(v0 - __bfloat162float(h0));
    __nv_bfloat16 l1 = __float2bfloat16(v1 - __bfloat162float(h1));
    __nv_bfloat162 ph; ph.x = h0; ph.y = h1;
    __nv_bfloat162 pl; pl.x = l0; pl.y = l1;
    hi = *reinterpret_cast<uint32_t*>(&ph);
    lo = *reinterpret_cast<uint32_t*>(&pl);
}

__device__ __forceinline__ void mma_bf16(float* c,
                                         const uint32_t* a,
                                         uint32_t b0, uint32_t b1) {
    asm volatile(
        "mma.sync.aligned.m16n8k16.row.col.f32.bf16.bf16.f32 "
        "{%0,%1,%2,%3}, {%4,%5,%6,%7}, {%8,%9}, {%0,%1,%2,%3};"
        : "+f"(c[0]), "+f"(c[1]), "+f"(c[2]), "+f"(c[3])
        : "r"(a[0]), "r"(a[1]), "r"(a[2]), "r"(a[3]), "r"(b0), "r"(b1));
}

// Load+split one 16x128 weight chunk (rows w*16..+16 of W) into Bh/Bl,
// transposed to [n][k]. All 256 threads.
__device__ __forceinline__ void load_w_chunk(const float* __restrict__ W,
                                             int w, char* smem) {
    const int tid = threadIdx.x;
    const int k  = tid >> 4;             // 0..15
    const int n0 = (tid & 15) * 8;       // 0..120
    const float4* src = reinterpret_cast<const float4*>(
        W + (size_t)(w * 16 + k) * D + n0);
    float4 v0 = __ldg(src);
    float4 v1 = __ldg(src + 1);
    float vv[8] = {v0.x, v0.y, v0.z, v0.w, v1.x, v1.y, v1.z, v1.w};
    __nv_bfloat16* bh = reinterpret_cast<__nv_bfloat16*>(smem + SM_BH);
    __nv_bfloat16* bl = reinterpret_cast<__nv_bfloat16*>(smem + SM_BL);
    #pragma unroll
    for (int j = 0; j < 8; j++) {
        __nv_bfloat16 h = __float2bfloat16(vv[j]);
        __nv_bfloat16 l = __float2bfloat16(vv[j] - __bfloat162float(h));
        bh[(n0 + j) * (2 * LDB32) + k] = h;
        bl[(n0 + j) * (2 * LDB32) + k] = l;
    }
}

__global__ void __launch_bounds__(256, 2)
mlp_mma_kernel(const float* __restrict__ H,
               const float* __restrict__ W1, const float* __restrict__ b1,
               const float* __restrict__ W2, const float* __restrict__ b2,
               float* __restrict__ out, int M) {
    extern __shared__ char smem[];
    uint32_t* ah32 = reinterpret_cast<uint32_t*>(smem + SM_AH);
    uint32_t* al32 = reinterpret_cast<uint32_t*>(smem + SM_AL);
    uint32_t* bh32 = reinterpret_cast<uint32_t*>(smem + SM_BH);
    uint32_t* bl32 = reinterpret_cast<uint32_t*>(smem + SM_BL);
    float* bias1 = reinterpret_cast<float*>(smem + SM_BIAS1);
    float* bias2 = reinterpret_cast<float*>(smem + SM_BIAS2);

    const int tid = threadIdx.x;
    const int wid = tid >> 5;
    const int lane = tid & 31;
    const int g = lane >> 2;             // group id 0..7
    const int t = lane & 3;              // thread-in-group 0..3
    const int warp_m = wid & 3;          // 4 m-groups of 32 rows
    const int warp_n = wid >> 2;         // 2 n-groups of 64 cols
    const int row_base = blockIdx.x * 128;

    // bias preload
    if (tid < 128) bias1[tid] = __ldg(b1 + tid);
    else           bias2[tid - 128] = __ldg(b2 + tid - 128);

    // ---- load H tile, split into Ah/Al ----
    {
        const int row = tid >> 1;                    // 0..127
        const int c0 = (tid & 1) * 64;
        const bool valid = (row_base + row) < M;
        const float4* src = reinterpret_cast<const float4*>(
            H + (size_t)(row_base + row) * D + c0);
        uint32_t* dh = ah32 + row * LDA32 + (c0 >> 1);
        uint32_t* dl = al32 + row * LDA32 + (c0 >> 1);
        #pragma unroll
        for (int q = 0; q < 16; q++) {
            float4 v = valid ? __ldg(src + q) : make_float4(0.f, 0.f, 0.f, 0.f);
            uint32_t h0, l0, h1, l1;
            split_pair(v.x, v.y, h0, l0);
            split_pair(v.z, v.w, h1, l1);
            dh[q * 2]     = h0;  dh[q * 2 + 1] = h1;
            dl[q * 2]     = l0;  dl[q * 2 + 1] = l1;
        }
    }

    float acc[2][8][4];
    #pragma unroll
    for (int i = 0; i < 2; i++)
        #pragma unroll
        for (int j = 0; j < 8; j++)
            #pragma unroll
            for (int c = 0; c < 4; c++) acc[i][j][c] = 0.f;

    // =============== GEMM1: h1 = H @ W1 ===============
    #pragma unroll 1
    for (int w = 0; w < 8; w++) {
        __syncthreads();
        load_w_chunk(W1, w, smem);
        __syncthreads();

        uint32_t ah[2][4], al[2][4];
        const int kw = w * 8;                        // uint32 col base
        #pragma unroll
        for (int mt = 0; mt < 2; mt++) {
            const int r0 = warp_m * 32 + mt * 16 + g;
            const uint32_t* ph = ah32 + r0 * LDA32 + kw + t;
            const uint32_t* pl = al32 + r0 * LDA32 + kw + t;
            ah[mt][0] = ph[0];  ah[mt][2] = ph[4];
            ah[mt][1] = ph[8 * LDA32];  ah[mt][3] = ph[8 * LDA32 + 4];
            al[mt][0] = pl[0];  al[mt][2] = pl[4];
            al[mt][1] = pl[8 * LDA32];  al[mt][3] = pl[8 * LDA32 + 4];
        }
        #pragma unroll
        for (int nt = 0; nt < 8; nt++) {
            const int nr = warp_n * 64 + nt * 8 + g;
            uint32_t bh0 = bh32[nr * LDB32 + t];
            uint32_t bh1 = bh32[nr * LDB32 + t + 4];
            uint32_t bl0 = bl32[nr * LDB32 + t];
            uint32_t bl1 = bl32[nr * LDB32 + t + 4];
            #pragma unroll
            for (int mt = 0; mt < 2; mt++) {
                mma_bf16(acc[mt][nt], ah[mt], bh0, bh1);
                mma_bf16(acc[mt][nt], al[mt], bh0, bh1);
                mma_bf16(acc[mt][nt], ah[mt], bl0, bl1);
            }
        }
    }

    // ---- epilogue 1: bias + relu, re-split into Ah/Al ----
    __syncthreads();
    #pragma unroll
    for (int mt = 0; mt < 2; mt++) {
        const int rl = warp_m * 32 + mt * 16 + g;
        #pragma unroll
        for (int nt = 0; nt < 8; nt++) {
            const int cb = warp_n * 64 + nt * 8 + t * 2;
            float v0 = fmaxf(acc[mt][nt][0] + bias1[cb],     0.f);
            float v1 = fmaxf(acc[mt][nt][1] + bias1[cb + 1], 0.f);
            float v2 = fmaxf(acc[mt][nt][2] + bias1[cb],     0.f);
            float v3 = fmaxf(acc[mt][nt][3] + bias1[cb + 1], 0.f);
            uint32_t hi, lo;
            split_pair(v0, v1, hi, lo);
            ah32[rl * LDA32 + (cb >> 1)] = hi;
            al32[rl * LDA32 + (cb >> 1)] = lo;
            split_pair(v2, v3, hi, lo);
            ah32[(rl + 8) * LDA32 + (cb >> 1)] = hi;
            al32[(rl + 8) * LDA32 + (cb >> 1)] = lo;
            acc[mt][nt][0] = 0.f; acc[mt][nt][1] = 0.f;
            acc[mt][nt][2] = 0.f; acc[mt][nt][3] = 0.f;
        }
    }

    // =============== GEMM2: out = h1 @ W2 ===============
    #pragma unroll 1
    for (int w = 0; w < 8; w++) {
        __syncthreads();
        load_w_chunk(W2, w, smem);
        __syncthreads();

        uint32_t ah[2][4], al[2][4];
        const int kw = w * 8;
        #pragma unroll
        for (int mt = 0; mt < 2; mt++) {
            const int r0 = warp_m * 32 + mt * 16 + g;
            const uint32_t* ph = ah32 + r0 * LDA32 + kw + t;
            const uint32_t* pl = al32 + r0 * LDA32 + kw + t;
            ah[mt][0] = ph[0];  ah[mt][2] = ph[4];
            ah[mt][1] = ph[8 * LDA32];  ah[mt][3] = ph[8 * LDA32 + 4];
            al[mt][0] = pl[0];  al[mt][2] = pl[4];
            al[mt][1] = pl[8 * LDA32];  al[mt][3] = pl[8 * LDA32 + 4];
        }
        #pragma unroll
        for (int nt = 0; nt < 8; nt++) {
            const int nr = warp_n * 64 + nt * 8 + g;
            uint32_t bh0 = bh32[nr * LDB32 + t];
            uint32_t bh1 = bh32[nr * LDB32 + t + 4];
            uint32_t bl0 = bl32[nr * LDB32 + t];
            uint32_t bl1 = bl32[nr * LDB32 + t + 4];
            #pragma unroll
            for (int mt = 0; mt < 2; mt++) {
                mma_bf16(acc[mt][nt], ah[mt], bh0, bh1);
                mma_bf16(acc[mt][nt], al[mt], bh0, bh1);
                mma_bf16(acc[mt][nt], ah[mt], bl0, bl1);
            }
        }
    }

    // ---- epilogue 2: bias -> out ----
    #pragma unroll
    for (int mt = 0; mt < 2; mt++) {
        const int rl = warp_m * 32 + mt * 16 + g;
        #pragma unroll
        for (int nt = 0; nt < 8; nt++) {
            const int cb = warp_n * 64 + nt * 8 + t * 2;
            if (row_base + rl < M) {
                float2 o;
                o.x = acc[mt][nt][0] + bias2[cb];
                o.y = acc[mt][nt][1] + bias2[cb + 1];
                *reinterpret_cast<float2*>(out + (size_t)(row_base + rl) * D + cb) = o;
            }
            if (row_base + rl + 8 < M) {
                float2 o;
                o.x = acc[mt][nt][2] + bias2[cb];
                o.y = acc[mt][nt][3] + bias2[cb + 1];
                *reinterpret_cast<float2*>(out + (size_t)(row_base + rl + 8) * D + cb) = o;
            }
        }
    }
}

extern "C" void kernel_launch(void* const* d_in, const int* in_sizes, int n_in,
                              void* d_out, int out_size) {
    const float* x  = (const float*)d_in[0];
    const void*  ei = d_in[1];
    const float* W1 = (const float*)d_in[2];
    const float* b1 = (const float*)d_in[3];
    const float* W2 = (const float*)d_in[4];
    const float* b2 = (const float*)d_in[5];
    float* out = (float*)d_out;

    const int N = in_sizes[0] / D;
    const int E = in_sizes[1] / 2;
    const int nb = (N + 1023) / 1024;

    float* p_h    = nullptr;
    int*   p_deg  = nullptr;
    int*   p_off  = nullptr;
    int*   p_cur  = nullptr;
    int*   p_csrc = nullptr;
    int*   p_bsum = nullptr;
    cudaGetSymbolAddress((void**)(&p_h),    g_h);
    cudaGetSymbolAddress((void**)(&p_deg),  g_degcnt);
    cudaGetSymbolAddress((void**)(&p_off),  g_off);
    cudaGetSymbolAddress((void**)(&p_cur),  g_cur);
    cudaGetSymbolAddress((void**)(&p_csrc), g_csrc);
    cudaGetSymbolAddress((void**)(&p_bsum), g_bsum);

    static int attr_set = 0;
    if (!attr_set) {
        cudaFuncSetAttribute(mlp_mma_kernel,
                             cudaFuncAttributeMaxDynamicSharedMemorySize,
                             SM_MLP_TOTAL);
        attr_set = 1;
    }

    detect_kernel<<<1, 32>>>((const int*)ei);

    zero_deg_kernel<<<(N + 255) / 256, 256>>>(p_deg, N);
    hist_kernel<<<(E + 255) / 256, 256>>>(ei, E, p_deg);
    scan_part_kernel<<<nb, 1024>>>(p_deg, p_off, p_bsum, N);
    scan_tops_kernel<<<1, 64>>>(p_bsum, nb);
    scan_add_kernel<<<nb, 1024>>>(p_off, p_cur, p_bsum, N, nb);
    fill_kernel<<<(E + 255) / 256, 256>>>(ei, E, p_cur, p_csrc);

    agg_kernel<<<(N + 7) / 8, 256>>>(x, p_csrc, p_off, p_h, N);

    int ntiles = (N + 127) / 128;
    mlp_mma_kernel<<<ntiles, 256, SM_MLP_TOTAL>>>(p_h, W1, b1, W2, b2, out, N);
}